// round 2
// baseline (speedup 1.0000x reference)
#include <cuda_runtime.h>
#include <math.h>

#define Bn   256
#define Hn   1024
#define XDn  192
#define YDn  64
#define INn  256
#define PREn 64
#define FWDn 48
#define G4H  4096

// ---------------- scratch (device globals; no allocations allowed) ----------
__device__ float g_h0[Bn * Hn];
__device__ float g_c0[Bn * Hn];
__device__ float g_h1[Bn * Hn];
__device__ float g_c1[Bn * Hn];
__device__ float g_z [Bn * G4H];
__device__ float g_t1[Bn * Hn];
__device__ float g_est[Bn * YDn];

// ---------------- helpers ----------------------------------------------------
__device__ __forceinline__ float to_tf32(float x) {
    float r;
    asm("cvt.rna.tf32.f32 %0, %1;" : "=f"(r) : "f"(x));
    return r;
}

__device__ __forceinline__ void mma_tf32(float c[4], const float a[4], const float b[2]) {
    asm volatile(
        "mma.sync.aligned.m16n8k8.row.col.f32.tf32.tf32.f32 "
        "{%0,%1,%2,%3}, {%4,%5,%6,%7}, {%8,%9}, {%0,%1,%2,%3};\n"
        : "+f"(c[0]), "+f"(c[1]), "+f"(c[2]), "+f"(c[3])
        : "r"(__float_as_uint(a[0])), "r"(__float_as_uint(a[1])),
          "r"(__float_as_uint(a[2])), "r"(__float_as_uint(a[3])),
          "r"(__float_as_uint(b[0])), "r"(__float_as_uint(b[1])));
}

__device__ __forceinline__ float sigf(float x) { return 1.0f / (1.0f + expf(-x)); }

// ---------------- 3xTF32 GEMM:  out(M=256 x N) = Acat(256 x K) @ Wcat^T
// Each operand split hi/lo: x = tf32(x) + tf32(x - tf32(x)).
// acc += A_lo*B_hi + A_hi*B_lo + A_hi*B_hi  (fp32 accumulate) -> ~fp32 precision.
// A is a concatenation along K of up to 3 row-major segments.
// W is a concatenation along K of up to 2 row-major (N x width) segments.
// act==1: out = tanh(acc + bias[n]); act==0: out = acc  (raw z, bias added later)
#define BM 64
#define BN 128
#define BK 16
#define PAD 4
#define BKp (BK + PAD)

__global__ __launch_bounds__(256) void gemm_3xtf32_kernel(
    const float* __restrict__ a0, int wa0, int lda0,
    const float* __restrict__ a1, int wa1, int lda1,
    const float* __restrict__ a2, int lda2,
    const float* __restrict__ w0, int wd0,
    const float* __restrict__ w1,
    int K, int N,
    float* __restrict__ out,
    const float* __restrict__ bias, int act)
{
    __shared__ float As_h[BM][BKp];
    __shared__ float As_l[BM][BKp];
    __shared__ float Ws_h[BN][BKp];
    __shared__ float Ws_l[BN][BKp];

    const int tid  = threadIdx.x;
    const int warp = tid >> 5;
    const int lane = tid & 31;
    const int m0 = blockIdx.y * BM;
    const int n0 = blockIdx.x * BN;
    const int wm = (warp & 1) * 32;   // warp tile 32(M) x 32(N); warps 2x4
    const int wn = (warp >> 1) * 32;
    const int w1ld = K - wd0;
    const int wa01 = wa0 + wa1;

    float acc[2][4][4];
#pragma unroll
    for (int mi = 0; mi < 2; mi++)
#pragma unroll
        for (int ni = 0; ni < 4; ni++)
#pragma unroll
            for (int e = 0; e < 4; e++) acc[mi][ni][e] = 0.0f;

    const int gr = lane >> 2;   // group id
    const int tg = lane & 3;    // thread-in-group

    for (int k0 = 0; k0 < K; k0 += BK) {
        // load A tile (segmented over K), split hi/lo
#pragma unroll
        for (int it = 0; it < (BM * BK) / 256; it++) {
            int idx = tid + it * 256;
            int r  = idx >> 4;
            int cc = idx & 15;
            int gm = m0 + r;
            int gk = k0 + cc;
            float v;
            if (gk < wa0)       v = a0[gm * lda0 + gk];
            else if (gk < wa01) v = a1[gm * lda1 + (gk - wa0)];
            else                v = a2[gm * lda2 + (gk - wa01)];
            float h = to_tf32(v);
            As_h[r][cc] = h;
            As_l[r][cc] = to_tf32(v - h);
        }
        // load W tile (segmented over K), split hi/lo
#pragma unroll
        for (int it = 0; it < (BN * BK) / 256; it++) {
            int idx = tid + it * 256;
            int r  = idx >> 4;
            int cc = idx & 15;
            int gn = n0 + r;
            int gk = k0 + cc;
            float v = (gk < wd0) ? w0[gn * wd0 + gk]
                                 : w1[gn * w1ld + (gk - wd0)];
            float h = to_tf32(v);
            Ws_h[r][cc] = h;
            Ws_l[r][cc] = to_tf32(v - h);
        }
        __syncthreads();

#pragma unroll
        for (int kk = 0; kk < BK; kk += 8) {
            float afh[2][4], afl[2][4];
            float bfh[4][2], bfl[4][2];
#pragma unroll
            for (int mi = 0; mi < 2; mi++) {
                int mrow = wm + mi * 16;
                afh[mi][0] = As_h[mrow + gr    ][kk + tg    ];
                afh[mi][1] = As_h[mrow + gr + 8][kk + tg    ];
                afh[mi][2] = As_h[mrow + gr    ][kk + tg + 4];
                afh[mi][3] = As_h[mrow + gr + 8][kk + tg + 4];
                afl[mi][0] = As_l[mrow + gr    ][kk + tg    ];
                afl[mi][1] = As_l[mrow + gr + 8][kk + tg    ];
                afl[mi][2] = As_l[mrow + gr    ][kk + tg + 4];
                afl[mi][3] = As_l[mrow + gr + 8][kk + tg + 4];
            }
#pragma unroll
            for (int ni = 0; ni < 4; ni++) {
                int nrow = wn + ni * 8;
                bfh[ni][0] = Ws_h[nrow + gr][kk + tg    ];
                bfh[ni][1] = Ws_h[nrow + gr][kk + tg + 4];
                bfl[ni][0] = Ws_l[nrow + gr][kk + tg    ];
                bfl[ni][1] = Ws_l[nrow + gr][kk + tg + 4];
            }
#pragma unroll
            for (int mi = 0; mi < 2; mi++)
#pragma unroll
                for (int ni = 0; ni < 4; ni++) {
                    mma_tf32(acc[mi][ni], afl[mi], bfh[ni]);
                    mma_tf32(acc[mi][ni], afh[mi], bfl[ni]);
                    mma_tf32(acc[mi][ni], afh[mi], bfh[ni]);
                }
        }
        __syncthreads();
    }

    // epilogue
#pragma unroll
    for (int mi = 0; mi < 2; mi++) {
#pragma unroll
        for (int ni = 0; ni < 4; ni++) {
            int row0 = m0 + wm + mi * 16 + gr;
            int col0 = n0 + wn + ni * 8 + tg * 2;
#pragma unroll
            for (int e = 0; e < 4; e++) {
                int r = row0 + (e >> 1) * 8;
                int c = col0 + (e & 1);
                float v = acc[mi][ni][e];
                if (act) v = tanhf(v + bias[c]);
                out[r * N + c] = v;
            }
        }
    }
}

// ---------------- LSTM cell elementwise (torch gate order i,f,g,o) ----------
__global__ __launch_bounds__(256) void lstm_cell_kernel(
    const float* __restrict__ z,
    const float* __restrict__ bi, const float* __restrict__ bh,
    float* __restrict__ h, float* __restrict__ c)
{
    int idx = blockIdx.x * 256 + threadIdx.x;   // over Bn*Hn
    int b = idx >> 10;
    int u = idx & 1023;
    const float* zr = z + b * G4H;
    float zi = zr[u           ] + bi[u           ] + bh[u           ];
    float zf = zr[u + Hn      ] + bi[u + Hn      ] + bh[u + Hn      ];
    float zg = zr[u + 2 * Hn  ] + bi[u + 2 * Hn  ] + bh[u + 2 * Hn  ];
    float zo = zr[u + 3 * Hn  ] + bi[u + 3 * Hn  ] + bh[u + 3 * Hn  ];
    float cn = sigf(zf) * c[idx] + sigf(zi) * tanhf(zg);
    c[idx] = cn;
    h[idx] = sigf(zo) * tanhf(cn);
}

// ---------------- fc2 + residual est update (warp per output, fp32) ----------
__global__ __launch_bounds__(256) void fc2_est_kernel(
    const float* __restrict__ t1, const float* __restrict__ w2,
    const float* __restrict__ b2, float* __restrict__ est,
    float* __restrict__ outp)
{
    int gw = (blockIdx.x * 256 + threadIdx.x) >> 5;   // global warp id, Bn*YDn of them
    int lane = threadIdx.x & 31;
    int b = gw >> 6;
    int j = gw & 63;
    const float* trow = t1 + b * Hn;
    const float* wrow = w2 + j * Hn;
    float s = 0.0f;
#pragma unroll 8
    for (int k = lane; k < Hn; k += 32) s += trow[k] * wrow[k];
#pragma unroll
    for (int o = 16; o; o >>= 1) s += __shfl_xor_sync(0xffffffffu, s, o);
    if (lane == 0) {
        float v = s + b2[j] + est[b * YDn + j];
        est[b * YDn + j] = v;
        outp[b * YDn + j] = v;
    }
}

// ---------------- init: zero states, est = pre_y[-1] -------------------------
__global__ __launch_bounds__(256) void init_kernel(const float* __restrict__ pre_y)
{
    int i = blockIdx.x * 256 + threadIdx.x;
    if (i < Bn * Hn) {
        g_h0[i] = 0.0f; g_c0[i] = 0.0f;
        g_h1[i] = 0.0f; g_c1[i] = 0.0f;
    }
    if (i < Bn * YDn) g_est[i] = pre_y[(PREn - 1) * Bn * YDn + i];
}

// ---------------- launch -----------------------------------------------------
extern "C" void kernel_launch(void* const* d_in, const int* in_sizes, int n_in,
                              void* d_out, int out_size)
{
    const float* pre_x  = (const float*)d_in[0];
    const float* pre_y  = (const float*)d_in[1];
    const float* fwd_x  = (const float*)d_in[2];
    const float* w_ih0  = (const float*)d_in[3];
    const float* w_hh0  = (const float*)d_in[4];
    const float* b_ih0  = (const float*)d_in[5];
    const float* b_hh0  = (const float*)d_in[6];
    const float* w_ih1  = (const float*)d_in[7];
    const float* w_hh1  = (const float*)d_in[8];
    const float* b_ih1  = (const float*)d_in[9];
    const float* b_hh1  = (const float*)d_in[10];
    const float* fc_w1  = (const float*)d_in[11];
    const float* fc_b1  = (const float*)d_in[12];
    const float* fc_w2  = (const float*)d_in[13];
    const float* fc_b2  = (const float*)d_in[14];
    float* outp = (float*)d_out;

    void *p_h0, *p_c0, *p_h1, *p_c1, *p_z, *p_t1, *p_est;
    cudaGetSymbolAddress(&p_h0, g_h0);
    cudaGetSymbolAddress(&p_c0, g_c0);
    cudaGetSymbolAddress(&p_h1, g_h1);
    cudaGetSymbolAddress(&p_c1, g_c1);
    cudaGetSymbolAddress(&p_z,  g_z);
    cudaGetSymbolAddress(&p_t1, g_t1);
    cudaGetSymbolAddress(&p_est, g_est);
    float* h0 = (float*)p_h0; float* c0 = (float*)p_c0;
    float* h1 = (float*)p_h1; float* c1 = (float*)p_c1;
    float* z  = (float*)p_z;  float* t1 = (float*)p_t1;
    float* est = (float*)p_est;

    dim3 gridZ(G4H / BN, Bn / BM);   // (32, 4) for lstm gate GEMMs
    dim3 gridF(Hn / BN, Bn / BM);    // (8, 4)  for fc1
    dim3 blk(256);
    int cellBlocks = (Bn * Hn) / 256;          // 1024
    int fc2Blocks  = (Bn * YDn * 32) / 256;    // 2048

    init_kernel<<<cellBlocks, blk>>>(pre_y);

    // ---------------- encode ----------------
    for (int t = 0; t < PREn; t++) {
        const float* xt = pre_x + (size_t)t * Bn * XDn;
        const float* yt = pre_y + (size_t)t * Bn * YDn;
        // layer 0: K = 192 + 64 + 1024 = 1280
        gemm_3xtf32_kernel<<<gridZ, blk>>>(
            xt, XDn, XDn, yt, YDn, YDn, h0, Hn,
            w_ih0, INn, w_hh0, INn + Hn, G4H, z, nullptr, 0);
        lstm_cell_kernel<<<cellBlocks, blk>>>(z, b_ih0, b_hh0, h0, c0);
        // layer 1: K = 1024 + 1024
        gemm_3xtf32_kernel<<<gridZ, blk>>>(
            h0, Hn, Hn, h1, Hn, Hn, h1, Hn,
            w_ih1, Hn, w_hh1, 2 * Hn, G4H, z, nullptr, 0);
        lstm_cell_kernel<<<cellBlocks, blk>>>(z, b_ih1, b_hh1, h1, c1);
    }

    // ---------------- decode ----------------
    for (int t = 0; t < FWDn; t++) {
        // fc1: t1 = tanh(h1 @ fc_w1^T + fc_b1)
        gemm_3xtf32_kernel<<<gridF, blk>>>(
            h1, Hn, Hn, h1, 0, Hn, h1, Hn,
            fc_w1, Hn, fc_w1, Hn, Hn, t1, fc_b1, 1);
        // fc2 + residual: est = t1 @ fc_w2^T + fc_b2 + est ; also writes output[t]
        fc2_est_kernel<<<fc2Blocks, blk>>>(t1, fc_w2, fc_b2, est,
                                           outp + (size_t)t * Bn * YDn);
        const float* xt = fwd_x + (size_t)t * Bn * XDn;
        // layer 0: K = 192 + 64 + 1024
        gemm_3xtf32_kernel<<<gridZ, blk>>>(
            xt, XDn, XDn, est, YDn, YDn, h0, Hn,
            w_ih0, INn, w_hh0, INn + Hn, G4H, z, nullptr, 0);
        lstm_cell_kernel<<<cellBlocks, blk>>>(z, b_ih0, b_hh0, h0, c0);
        // layer 1
        gemm_3xtf32_kernel<<<gridZ, blk>>>(
            h0, Hn, Hn, h1, Hn, Hn, h1, Hn,
            w_ih1, Hn, w_hh1, 2 * Hn, G4H, z, nullptr, 0);
        lstm_cell_kernel<<<cellBlocks, blk>>>(z, b_ih1, b_hh1, h1, c1);
    }
}

// round 3
// speedup vs baseline: 3.6320x; 3.6320x over previous
#include <cuda_runtime.h>
#include <cuda_fp16.h>
#include <math.h>

#define Bn   256
#define Hn   1024
#define XDn  192
#define YDn  64
#define INn  256
#define PREn 64
#define FWDn 48
#define G4H  4096

// ---------------- scratch (device globals; no allocations allowed) ----------
// packed hi/lo half weights:  W0 = [w_ih0 | w_hh0]  (4096 x 1280)
//                             W1 = [w_ih1 | w_hh1]  (4096 x 2048)
//                             Wf = fc_w1            (1024 x 1024)
__device__ __half g_W0h[G4H * 1280], g_W0l[G4H * 1280];
__device__ __half g_W1h[G4H * 2048], g_W1l[G4H * 2048];
__device__ __half g_Wfh[Hn * Hn],    g_Wfl[Hn * Hn];
// encode inputs [x_t|y_t] split per step: (64, 256, 256)
__device__ __half g_XYh[PREn * Bn * INn], g_XYl[PREn * Bn * INn];
// decode inputs [fx_t|est_t]: (48, 256, 256); est section filled at runtime
__device__ __half g_FXh[FWDn * Bn * INn], g_FXl[FWDn * Bn * INn];
// hidden states as hi/lo halves
__device__ __half g_H0h[Bn * Hn], g_H0l[Bn * Hn];
__device__ __half g_H1h[Bn * Hn], g_H1l[Bn * Hn];
// fp32 state
__device__ float g_c0[Bn * Hn], g_c1[Bn * Hn];
__device__ float g_z[Bn * G4H], g_t1[Bn * Hn], g_est[Bn * YDn];

// ---------------- helpers ----------------------------------------------------
__device__ __forceinline__ float sigf(float x) { return 1.0f / (1.0f + expf(-x)); }

__device__ __forceinline__ void cpa16(void* dst, const void* src) {
    unsigned d = (unsigned)__cvta_generic_to_shared(dst);
    asm volatile("cp.async.cg.shared.global [%0], [%1], 16;\n" :: "r"(d), "l"(src));
}

__device__ __forceinline__ void mma16816(float c[4], const unsigned a[4], const unsigned b[2]) {
    asm volatile(
        "mma.sync.aligned.m16n8k16.row.col.f32.f16.f16.f32 "
        "{%0,%1,%2,%3}, {%4,%5,%6,%7}, {%8,%9}, {%0,%1,%2,%3};\n"
        : "+f"(c[0]), "+f"(c[1]), "+f"(c[2]), "+f"(c[3])
        : "r"(a[0]), "r"(a[1]), "r"(a[2]), "r"(a[3]), "r"(b[0]), "r"(b[1]));
}

// ---------------- fp16x3 GEMM:  out(256 x N) = Acat(256 x K) @ W^T ----------
// A: 2 K-segments of precomputed hi/lo halves.  W: packed [N][K] hi/lo halves.
// acc += A_lo*W_hi + A_hi*W_lo + A_hi*W_hi  (fp32 accumulate).
#define BM 64
#define BN 128
#define BK 32            // halves per k tile
#define RS 20            // smem row stride in 4B units (16 data + 4 pad)
#define OFF_AH 0
#define OFF_AL (BM * RS)                  // 1280
#define OFF_WH (2 * BM * RS)              // 2560
#define OFF_WL (2 * BM * RS + BN * RS)    // 5120
#define STAGE  (2 * BM * RS + 2 * BN * RS) // 7680 (4B units); 2 stages = 61440 B

__device__ __forceinline__ void load_tile(
    unsigned* sm, int sbase, int k0, int m0, int n0, int tid,
    const __half* a0h, const __half* a0l, int w0, int lda0,
    const __half* a1h, const __half* a1l, int lda1,
    const __half* wgh, const __half* wgl, int ldw)
{
    const __half *ah, *al; int lda, koff;
    if (k0 < w0) { ah = a0h; al = a0l; lda = lda0; koff = k0; }
    else         { ah = a1h; al = a1l; lda = lda1; koff = k0 - w0; }
#pragma unroll
    for (int i = 0; i < 2; i++) {           // A: 512 16B chunks (hi+lo)
        int c = tid + (i << 8);
        int part = c >> 8;
        int row  = (c & 255) >> 2;
        int kc   = c & 3;
        const __half* src = (part ? al : ah) + (size_t)(m0 + row) * lda + koff + kc * 8;
        unsigned* dst = sm + sbase + (part ? OFF_AL : OFF_AH) + row * RS + kc * 4;
        cpa16(dst, src);
    }
#pragma unroll
    for (int i = 0; i < 4; i++) {           // W: 1024 16B chunks (hi+lo)
        int c = tid + (i << 8);
        int part = c >> 9;
        int row  = (c & 511) >> 2;
        int kc   = c & 3;
        const __half* src = (part ? wgl : wgh) + (size_t)(n0 + row) * ldw + k0 + kc * 8;
        unsigned* dst = sm + sbase + (part ? OFF_WL : OFF_WH) + row * RS + kc * 4;
        cpa16(dst, src);
    }
}

__global__ void __launch_bounds__(256) gemm_fp16x3(
    const __half* __restrict__ a0h, const __half* __restrict__ a0l, int w0, int lda0,
    const __half* __restrict__ a1h, const __half* __restrict__ a1l, int lda1,
    const __half* __restrict__ wgh, const __half* __restrict__ wgl, int ldw,
    int K, int N,
    float* __restrict__ out,
    const float* __restrict__ bias, int act)
{
    extern __shared__ unsigned sm[];
    const int tid  = threadIdx.x;
    const int warp = tid >> 5;
    const int lane = tid & 31;
    const int m0 = blockIdx.y * BM;
    const int n0 = blockIdx.x * BN;
    const int wm = (warp & 1) * 32;    // warps 2(M) x 4(N); warp tile 32x32
    const int wn = (warp >> 1) * 32;
    const int gr = lane >> 2;
    const int tg = lane & 3;

    float acc[2][4][4];
#pragma unroll
    for (int mi = 0; mi < 2; mi++)
#pragma unroll
        for (int ni = 0; ni < 4; ni++)
#pragma unroll
            for (int e = 0; e < 4; e++) acc[mi][ni][e] = 0.0f;

    const int NT = K / BK;
    load_tile(sm, 0, 0, m0, n0, tid, a0h, a0l, w0, lda0, a1h, a1l, lda1, wgh, wgl, ldw);
    asm volatile("cp.async.commit_group;\n");

    for (int kt = 0; kt < NT; kt++) {
        if (kt + 1 < NT) {
            load_tile(sm, ((kt + 1) & 1) * STAGE, (kt + 1) * BK, m0, n0, tid,
                      a0h, a0l, w0, lda0, a1h, a1l, lda1, wgh, wgl, ldw);
            asm volatile("cp.async.commit_group;\n");
            asm volatile("cp.async.wait_group 1;\n");
        } else {
            asm volatile("cp.async.wait_group 0;\n");
        }
        __syncthreads();

        const int sb = (kt & 1) * STAGE;
        const unsigned* pAh = sm + sb + OFF_AH;
        const unsigned* pAl = sm + sb + OFF_AL;
        const unsigned* pWh = sm + sb + OFF_WH;
        const unsigned* pWl = sm + sb + OFF_WL;
#pragma unroll
        for (int ks = 0; ks < 2; ks++) {
            const int jb = ks * 8;
            unsigned ah[2][4], al[2][4], bh[4][2], bl[4][2];
#pragma unroll
            for (int mi = 0; mi < 2; mi++) {
                int r0 = (wm + mi * 16 + gr) * RS + jb + tg;
                int r1 = (wm + mi * 16 + gr + 8) * RS + jb + tg;
                ah[mi][0] = pAh[r0];     ah[mi][1] = pAh[r1];
                ah[mi][2] = pAh[r0 + 4]; ah[mi][3] = pAh[r1 + 4];
                al[mi][0] = pAl[r0];     al[mi][1] = pAl[r1];
                al[mi][2] = pAl[r0 + 4]; al[mi][3] = pAl[r1 + 4];
            }
#pragma unroll
            for (int ni = 0; ni < 4; ni++) {
                int rn = (wn + ni * 8 + gr) * RS + jb + tg;
                bh[ni][0] = pWh[rn]; bh[ni][1] = pWh[rn + 4];
                bl[ni][0] = pWl[rn]; bl[ni][1] = pWl[rn + 4];
            }
#pragma unroll
            for (int mi = 0; mi < 2; mi++)
#pragma unroll
                for (int ni = 0; ni < 4; ni++) {
                    mma16816(acc[mi][ni], al[mi], bh[ni]);
                    mma16816(acc[mi][ni], ah[mi], bl[ni]);
                    mma16816(acc[mi][ni], ah[mi], bh[ni]);
                }
        }
        __syncthreads();
    }

    // epilogue
#pragma unroll
    for (int mi = 0; mi < 2; mi++) {
#pragma unroll
        for (int ni = 0; ni < 4; ni++) {
            int row0 = m0 + wm + mi * 16 + gr;
            int col0 = n0 + wn + ni * 8 + tg * 2;
#pragma unroll
            for (int e = 0; e < 4; e++) {
                int r = row0 + (e >> 1) * 8;
                int c = col0 + (e & 1);
                float v = acc[mi][ni][e];
                if (act) v = tanhf(v + bias[c]);
                out[r * N + c] = v;
            }
        }
    }
}

// ---------------- hi/lo split with strided packing ---------------------------
// src fp32 [n][w] row-major -> dst half [n][ldd] at column offset off.
__global__ void __launch_bounds__(256) split_kernel(
    const float* __restrict__ src, __half* __restrict__ dh, __half* __restrict__ dl,
    int w, int ldd, int off, int total)
{
    for (int idx = blockIdx.x * 256 + threadIdx.x; idx < total; idx += gridDim.x * 256) {
        int n = idx / w;
        int k = idx - n * w;
        float v = src[idx];
        __half h = __float2half_rn(v);
        int d = n * ldd + off + k;
        dh[d] = h;
        dl[d] = __float2half_rn(v - __half2float(h));
    }
}

// ---------------- LSTM cell: gates + write h as hi/lo halves -----------------
__global__ void __launch_bounds__(256) lstm_cell_kernel(
    const float* __restrict__ z,
    const float* __restrict__ bi, const float* __restrict__ bh,
    float* __restrict__ c, __half* __restrict__ dh, __half* __restrict__ dl)
{
    int idx = blockIdx.x * 256 + threadIdx.x;   // over Bn*Hn
    int b = idx >> 10;
    int u = idx & 1023;
    const float* zr = z + b * G4H;
    float zi = zr[u          ] + bi[u          ] + bh[u          ];
    float zf = zr[u + Hn     ] + bi[u + Hn     ] + bh[u + Hn     ];
    float zg = zr[u + 2 * Hn ] + bi[u + 2 * Hn ] + bh[u + 2 * Hn ];
    float zo = zr[u + 3 * Hn ] + bi[u + 3 * Hn ] + bh[u + 3 * Hn ];
    float cn = sigf(zf) * c[idx] + sigf(zi) * tanhf(zg);
    c[idx] = cn;
    float hn = sigf(zo) * tanhf(cn);
    __half hh = __float2half_rn(hn);
    dh[idx] = hh;
    dl[idx] = __float2half_rn(hn - __half2float(hh));
}

// ---------------- fc2 + residual est; writes output + est halves into FXE ----
__global__ void __launch_bounds__(256) fc2_est_kernel(
    const float* __restrict__ t1, const float* __restrict__ w2,
    const float* __restrict__ b2, float* __restrict__ est,
    float* __restrict__ outp, __half* __restrict__ fh, __half* __restrict__ fl)
{
    int gw = (blockIdx.x * 256 + threadIdx.x) >> 5;
    int lane = threadIdx.x & 31;
    int b = gw >> 6;
    int j = gw & 63;
    const float* trow = t1 + b * Hn;
    const float* wrow = w2 + j * Hn;
    float s = 0.0f;
#pragma unroll 8
    for (int k = lane; k < Hn; k += 32) s += trow[k] * wrow[k];
#pragma unroll
    for (int o = 16; o; o >>= 1) s += __shfl_xor_sync(0xffffffffu, s, o);
    if (lane == 0) {
        float v = s + b2[j] + est[b * YDn + j];
        est[b * YDn + j] = v;
        outp[b * YDn + j] = v;
        __half hh = __float2half_rn(v);
        int d = b * INn + XDn + j;
        fh[d] = hh;
        fl[d] = __float2half_rn(v - __half2float(hh));
    }
}

// ---------------- init: zero states, est = pre_y[-1] -------------------------
__global__ void __launch_bounds__(256) init_kernel(const float* __restrict__ pre_y)
{
    int i = blockIdx.x * 256 + threadIdx.x;
    if (i < Bn * Hn) {
        g_c0[i] = 0.0f; g_c1[i] = 0.0f;
        g_H0h[i] = __float2half_rn(0.0f); g_H0l[i] = __float2half_rn(0.0f);
        g_H1h[i] = __float2half_rn(0.0f); g_H1l[i] = __float2half_rn(0.0f);
    }
    if (i < Bn * YDn) g_est[i] = pre_y[(PREn - 1) * Bn * YDn + i];
}

// ---------------- launch -----------------------------------------------------
extern "C" void kernel_launch(void* const* d_in, const int* in_sizes, int n_in,
                              void* d_out, int out_size)
{
    const float* pre_x  = (const float*)d_in[0];
    const float* pre_y  = (const float*)d_in[1];
    const float* fwd_x  = (const float*)d_in[2];
    const float* w_ih0  = (const float*)d_in[3];
    const float* w_hh0  = (const float*)d_in[4];
    const float* b_ih0  = (const float*)d_in[5];
    const float* b_hh0  = (const float*)d_in[6];
    const float* w_ih1  = (const float*)d_in[7];
    const float* w_hh1  = (const float*)d_in[8];
    const float* b_ih1  = (const float*)d_in[9];
    const float* b_hh1  = (const float*)d_in[10];
    const float* fc_w1  = (const float*)d_in[11];
    const float* fc_b1  = (const float*)d_in[12];
    const float* fc_w2  = (const float*)d_in[13];
    const float* fc_b2  = (const float*)d_in[14];
    float* outp = (float*)d_out;

    cudaFuncSetAttribute(gemm_fp16x3, cudaFuncAttributeMaxDynamicSharedMemorySize,
                         2 * STAGE * 4);

    void *pv;
    #define SYM(name, var) cudaGetSymbolAddress(&pv, var); auto* name = (decltype(&var[0]))pv;
    SYM(W0h, g_W0h) SYM(W0l, g_W0l) SYM(W1h, g_W1h) SYM(W1l, g_W1l)
    SYM(Wfh, g_Wfh) SYM(Wfl, g_Wfl)
    SYM(XYh, g_XYh) SYM(XYl, g_XYl) SYM(FXh, g_FXh) SYM(FXl, g_FXl)
    SYM(H0h, g_H0h) SYM(H0l, g_H0l) SYM(H1h, g_H1h) SYM(H1l, g_H1l)
    SYM(c0, g_c0) SYM(c1, g_c1) SYM(z, g_z) SYM(t1, g_t1) SYM(est, g_est)
    #undef SYM

    dim3 blk(256);
    dim3 gridZ(G4H / BN, Bn / BM);   // (32, 4)
    dim3 gridF(Hn / BN, Bn / BM);    // (8, 4)
    int cellBlocks = (Bn * Hn) / 256;
    int fc2Blocks  = (Bn * YDn * 32) / 256;
    int splitBlocks = 2048;
    unsigned smemB = 2 * STAGE * 4;  // 61440

    // one-time per launch: pack + split weights and static inputs
    split_kernel<<<splitBlocks, blk>>>(w_ih0, W0h, W0l, INn, 1280, 0,   G4H * INn);
    split_kernel<<<splitBlocks, blk>>>(w_hh0, W0h, W0l, Hn,  1280, INn, G4H * Hn);
    split_kernel<<<splitBlocks, blk>>>(w_ih1, W1h, W1l, Hn,  2048, 0,   G4H * Hn);
    split_kernel<<<splitBlocks, blk>>>(w_hh1, W1h, W1l, Hn,  2048, Hn,  G4H * Hn);
    split_kernel<<<splitBlocks, blk>>>(fc_w1, Wfh, Wfl, Hn,  1024, 0,   Hn * Hn);
    split_kernel<<<splitBlocks, blk>>>(pre_x, XYh, XYl, XDn, INn, 0,    PREn * Bn * XDn);
    split_kernel<<<splitBlocks, blk>>>(pre_y, XYh, XYl, YDn, INn, XDn,  PREn * Bn * YDn);
    split_kernel<<<splitBlocks, blk>>>(fwd_x, FXh, FXl, XDn, INn, 0,    FWDn * Bn * XDn);
    init_kernel<<<cellBlocks, blk>>>(pre_y);

    // ---------------- encode ----------------
    for (int t = 0; t < PREn; t++) {
        const __half* xyh = XYh + (size_t)t * Bn * INn;
        const __half* xyl = XYl + (size_t)t * Bn * INn;
        gemm_fp16x3<<<gridZ, blk, smemB>>>(
            xyh, xyl, INn, INn, H0h, H0l, Hn,
            W0h, W0l, 1280, 1280, G4H, z, nullptr, 0);
        lstm_cell_kernel<<<cellBlocks, blk>>>(z, b_ih0, b_hh0, c0, H0h, H0l);
        gemm_fp16x3<<<gridZ, blk, smemB>>>(
            H0h, H0l, Hn, Hn, H1h, H1l, Hn,
            W1h, W1l, 2048, 2048, G4H, z, nullptr, 0);
        lstm_cell_kernel<<<cellBlocks, blk>>>(z, b_ih1, b_hh1, c1, H1h, H1l);
    }

    // ---------------- decode ----------------
    for (int t = 0; t < FWDn; t++) {
        __half* fxh = FXh + (size_t)t * Bn * INn;
        __half* fxl = FXl + (size_t)t * Bn * INn;
        // fc1: t1 = tanh(h1 @ fc_w1^T + fc_b1)
        gemm_fp16x3<<<gridF, blk, smemB>>>(
            H1h, H1l, Hn, Hn, H1h, H1l, Hn,
            Wfh, Wfl, Hn, Hn, Hn, t1, fc_b1, 1);
        // fc2 + residual; writes output[t] and est halves into FXE[t]
        fc2_est_kernel<<<fc2Blocks, blk>>>(t1, fc_w2, fc_b2, est,
                                           outp + (size_t)t * Bn * YDn, fxh, fxl);
        gemm_fp16x3<<<gridZ, blk, smemB>>>(
            fxh, fxl, INn, INn, H0h, H0l, Hn,
            W0h, W0l, 1280, 1280, G4H, z, nullptr, 0);
        lstm_cell_kernel<<<cellBlocks, blk>>>(z, b_ih0, b_hh0, c0, H0h, H0l);
        gemm_fp16x3<<<gridZ, blk, smemB>>>(
            H0h, H0l, Hn, Hn, H1h, H1l, Hn,
            W1h, W1l, 2048, 2048, G4H, z, nullptr, 0);
        lstm_cell_kernel<<<cellBlocks, blk>>>(z, b_ih1, b_hh1, c1, H1h, H1l);
    }
}